// round 2
// baseline (speedup 1.0000x reference)
#include <cuda_runtime.h>
#include <math.h>

#define LSEQ 256
#define BDIM 128
#define DDIM 2048
#define HDIM 2048
#define BH   (BDIM * HDIM)      /* 262144 */
#define LBH  (LSEQ * BH)        /* 67108864 */

/* ---------------- packed f32x2 helpers (Blackwell dual-rate fp32) -------- */

__device__ __forceinline__ unsigned long long splat2(float x) {
    unsigned long long r;
    asm("mov.b64 %0, {%1, %1};" : "=l"(r) : "f"(x));
    return r;
}
__device__ __forceinline__ unsigned long long pack2(float lo, float hi) {
    unsigned long long r;
    asm("mov.b64 %0, {%1, %2};" : "=l"(r) : "f"(lo), "f"(hi));
    return r;
}
__device__ __forceinline__ void ffma2(unsigned long long &d,
                                      unsigned long long a,
                                      unsigned long long b) {
    asm("fma.rn.f32x2 %0, %1, %2, %0;" : "+l"(d) : "l"(a), "l"(b));
}
__device__ __forceinline__ float2 unpack2(unsigned long long v) {
    float2 f;
    asm("mov.b64 {%0, %1}, %2;" : "=f"(f.x), "=f"(f.y) : "l"(v));
    return f;
}

/* ---------------- Kernel 1: xp = inputs @ W_ih + b  ->  out[0:LBH) ------- */
/* A: [M=LSEQ*BDIM, K=DDIM] row-major; W: [K, N=HDIM] row-major.            */
/* 128x128 CTA tile, BK=16, 256 threads, 8x8 per thread, FFMA2 inner loop.  */

__global__ void __launch_bounds__(256, 2) xp_gemm(
    const float* __restrict__ A, const float* __restrict__ W,
    const float* __restrict__ bias, float* __restrict__ C)
{
    __shared__ float As[16][132];   /* A tile transposed, padded            */
    __shared__ float Bs[16][128];

    const int tid = threadIdx.x;
    const int bm = blockIdx.y * 128;
    const int bn = blockIdx.x * 128;
    const int tx = tid & 15, ty = tid >> 4;

    /* global-load assignments */
    const int ar = tid >> 2, af = (tid & 3) << 2;     /* A: row 0..63, col f4 */
    const int br = tid >> 5, bc = (tid & 31) << 2;    /* B: row 0..7,  col f4 */

    unsigned long long acc[8][4];
    {   /* init accumulators with bias (applied exactly once) */
        const float* bb = bias + bn + tx * 8;
        unsigned long long b0 = pack2(bb[0], bb[1]);
        unsigned long long b1 = pack2(bb[2], bb[3]);
        unsigned long long b2 = pack2(bb[4], bb[5]);
        unsigned long long b3 = pack2(bb[6], bb[7]);
        #pragma unroll
        for (int i = 0; i < 8; i++) {
            acc[i][0] = b0; acc[i][1] = b1; acc[i][2] = b2; acc[i][3] = b3;
        }
    }

    for (int kt = 0; kt < DDIM; kt += 16) {
        float4 a0 = *(const float4*)(A + (size_t)(bm + ar)      * DDIM + kt + af);
        float4 a1 = *(const float4*)(A + (size_t)(bm + ar + 64) * DDIM + kt + af);
        float4 b0 = *(const float4*)(W + (size_t)(kt + br)     * HDIM + bn + bc);
        float4 b1 = *(const float4*)(W + (size_t)(kt + br + 8) * HDIM + bn + bc);
        __syncthreads();
        As[af + 0][ar] = a0.x; As[af + 1][ar] = a0.y;
        As[af + 2][ar] = a0.z; As[af + 3][ar] = a0.w;
        As[af + 0][ar + 64] = a1.x; As[af + 1][ar + 64] = a1.y;
        As[af + 2][ar + 64] = a1.z; As[af + 3][ar + 64] = a1.w;
        *(float4*)&Bs[br][bc]     = b0;
        *(float4*)&Bs[br + 8][bc] = b1;
        __syncthreads();

        #pragma unroll
        for (int k = 0; k < 16; k++) {
            float4 av0 = *(const float4*)&As[k][ty * 8];
            float4 av1 = *(const float4*)&As[k][ty * 8 + 4];
            const unsigned long long* wb =
                (const unsigned long long*)&Bs[k][tx * 8];
            unsigned long long w0 = wb[0], w1 = wb[1], w2 = wb[2], w3 = wb[3];
            float a[8] = {av0.x, av0.y, av0.z, av0.w,
                          av1.x, av1.y, av1.z, av1.w};
            #pragma unroll
            for (int i = 0; i < 8; i++) {
                unsigned long long ai = splat2(a[i]);
                ffma2(acc[i][0], ai, w0);
                ffma2(acc[i][1], ai, w1);
                ffma2(acc[i][2], ai, w2);
                ffma2(acc[i][3], ai, w3);
            }
        }
    }

    #pragma unroll
    for (int i = 0; i < 8; i++) {
        int m = bm + ty * 8 + i;
        float2 r0 = unpack2(acc[i][0]);
        float2 r1 = unpack2(acc[i][1]);
        float2 r2 = unpack2(acc[i][2]);
        float2 r3 = unpack2(acc[i][3]);
        float* cp = C + (size_t)m * HDIM + bn + tx * 8;
        *(float4*)(cp)     = make_float4(r0.x, r0.y, r1.x, r1.y);
        *(float4*)(cp + 4) = make_float4(r2.x, r2.y, r3.x, r3.y);
    }
}

/* ---------------- Kernel 2: scan step t (t >= 1) ------------------------- */
/* h = out[t-1] (B x H), in/out tile = out[t] (holds xp, becomes h_new).    */
/* 128 CTAs x 16 cols. 8 warps; warp w owns rows 16w..16w+15; 2 lanes/row,  */
/* 8 cols per lane as 4 f32x2 pairs. h and W chunks double-buffered in SMEM */
/* with register prefetch, one __syncthreads per 32-k chunk.                */

#define KC 32
#define NCHUNK (HDIM / KC)      /* 64 */

__global__ void __launch_bounds__(256) rnn_step(
    const float* __restrict__ Whh, float* __restrict__ out, int t)
{
    __shared__ float hs[2][BDIM][KC + 4];   /* 36 KB, padded rows (stride 36) */
    __shared__ float ws[2][KC][16];         /* 4 KB                           */

    const int tid   = threadIdx.x;
    const int c0    = blockIdx.x * 16;
    const int w     = tid >> 5;
    const int lane  = tid & 31;
    const int row   = (w << 4) + (lane >> 1);
    const int chalf = lane & 1;

    const float* __restrict__ h = out + (size_t)(t - 1) * BH;
    float* o = out + (size_t)t * BH;

    /* staging assignments: h tile = 128 rows x 32 floats = 1024 float4,
       4 per thread; W tile = 32 x 16 floats = 128 float4, threads < 128 */
    const int hf  = (tid & 7) << 2;     /* 0,4,...,28 */
    const int hrb = tid >> 3;           /* 0..31      */
    const int wr  = tid >> 2;           /* 0..63 (use <32 via tid<128) */
    const int wf  = (tid & 3) << 2;

    /* prologue: stage chunk 0 into buffer 0 */
    #pragma unroll
    for (int it = 0; it < 4; it++) {
        int r = hrb + 32 * it;
        float4 v = *(const float4*)(h + (size_t)r * HDIM + hf);
        *(float4*)&hs[0][r][hf] = v;
    }
    if (tid < 128) {
        float4 v = *(const float4*)(Whh + (size_t)wr * HDIM + c0 + wf);
        *(float4*)&ws[0][wr][wf] = v;
    }
    __syncthreads();

    unsigned long long acc[4] = {0ull, 0ull, 0ull, 0ull};
    int cur = 0;
    for (int kt = 0; kt < NCHUNK; kt++) {
        const bool more = (kt + 1 < NCHUNK);
        const int k0n = (kt + 1) * KC;
        float4 gh0, gh1, gh2, gh3, gw;
        if (more) {     /* prefetch next chunk into registers */
            gh0 = *(const float4*)(h + (size_t)(hrb)      * HDIM + k0n + hf);
            gh1 = *(const float4*)(h + (size_t)(hrb + 32) * HDIM + k0n + hf);
            gh2 = *(const float4*)(h + (size_t)(hrb + 64) * HDIM + k0n + hf);
            gh3 = *(const float4*)(h + (size_t)(hrb + 96) * HDIM + k0n + hf);
            if (tid < 128)
                gw = *(const float4*)(Whh + (size_t)(k0n + wr) * HDIM + c0 + wf);
        }

        /* compute on buffer `cur` */
        const float* hrow = &hs[cur][row][0];
        #pragma unroll
        for (int kk = 0; kk < KC; kk += 4) {
            float4 hv = *(const float4*)(hrow + kk);
            #pragma unroll
            for (int u = 0; u < 4; u++) {
                unsigned long long hh = splat2(((const float*)&hv)[u]);
                const unsigned long long* wp =
                    (const unsigned long long*)&ws[cur][kk + u][chalf * 8];
                ffma2(acc[0], hh, wp[0]);
                ffma2(acc[1], hh, wp[1]);
                ffma2(acc[2], hh, wp[2]);
                ffma2(acc[3], hh, wp[3]);
            }
        }

        if (more) {     /* store prefetch into the other buffer; one sync */
            int nxt = cur ^ 1;
            *(float4*)&hs[nxt][hrb]     [hf] = gh0;
            *(float4*)&hs[nxt][hrb + 32][hf] = gh1;
            *(float4*)&hs[nxt][hrb + 64][hf] = gh2;
            *(float4*)&hs[nxt][hrb + 96][hf] = gh3;
            if (tid < 128) *(float4*)&ws[nxt][wr][wf] = gw;
            __syncthreads();
            cur = nxt;
        }
    }

    /* epilogue: h_new = tanh(xp + h @ W) in place */
    float* orow = o + (size_t)row * HDIM + c0 + chalf * 8;
    float2 r0 = unpack2(acc[0]);
    float2 r1 = unpack2(acc[1]);
    float2 r2 = unpack2(acc[2]);
    float2 r3 = unpack2(acc[3]);
    orow[0] = tanhf(orow[0] + r0.x);
    orow[1] = tanhf(orow[1] + r0.y);
    orow[2] = tanhf(orow[2] + r1.x);
    orow[3] = tanhf(orow[3] + r1.y);
    orow[4] = tanhf(orow[4] + r2.x);
    orow[5] = tanhf(orow[5] + r2.y);
    orow[6] = tanhf(orow[6] + r3.x);
    orow[7] = tanhf(orow[7] + r3.y);
}

/* ---------------- Kernel 3: step 0 is just tanh(xp[0]) (h0 = 0) ---------- */

__global__ void tanh0(float* __restrict__ out) {
    int i = blockIdx.x * blockDim.x + threadIdx.x;
    if (i < BH) out[i] = tanhf(out[i]);
}

/* ---------------- Kernel 4: final_state = outputs[L-1] ------------------- */

__global__ void copy_final(float* __restrict__ out) {
    int i = blockIdx.x * blockDim.x + threadIdx.x;
    if (i < BH) out[(size_t)LBH + i] = out[(size_t)(LSEQ - 1) * BH + i];
}

/* ---------------- launch ------------------------------------------------- */

extern "C" void kernel_launch(void* const* d_in, const int* in_sizes, int n_in,
                              void* d_out, int out_size) {
    const float* inputs = (const float*)d_in[0];
    const float* W_ih   = (const float*)d_in[1];
    const float* W_hh   = (const float*)d_in[2];
    const float* bias   = (const float*)d_in[3];
    float* out = (float*)d_out;

    /* xp = inputs @ W_ih + b, written straight into the outputs slab */
    dim3 grid(HDIM / 128, (LSEQ * BDIM) / 128);   /* (16, 256) */
    xp_gemm<<<grid, 256>>>(inputs, W_ih, bias, out);

    /* t = 0: h0 = 0, so out[0] = tanh(xp[0]) */
    tanh0<<<(BH + 255) / 256, 256>>>(out);

    /* t = 1..L-1: out[t] = tanh(out[t] + out[t-1] @ W_hh) */
    for (int t = 1; t < LSEQ; t++)
        rnn_step<<<HDIM / 16, 256>>>(W_hh, out, t);

    /* trailing final_state, if the output buffer includes it */
    if (out_size >= LBH + BH)
        copy_final<<<(BH + 255) / 256, 256>>>(out);
}

// round 3
// speedup vs baseline: 1.6707x; 1.6707x over previous
#include <cuda_runtime.h>
#include <math.h>

#define LSEQ 256
#define BDIM 128
#define DDIM 2048
#define HDIM 2048
#define BH   (BDIM * HDIM)      /* 262144 */
#define LBH  (LSEQ * BH)        /* 67108864 */
#define KSPLIT 8
#define KCHUNK (HDIM / KSPLIT)  /* 256 */

/* split-K partial accumulator scratch: 8 * 128 * 2048 floats = 8 MB */
__device__ float g_part[(size_t)KSPLIT * BH];

/* ---------------- packed f32x2 helpers (Blackwell dual-rate fp32) -------- */

__device__ __forceinline__ unsigned long long splat2(float x) {
    unsigned long long r;
    asm("mov.b64 %0, {%1, %1};" : "=l"(r) : "f"(x));
    return r;
}
__device__ __forceinline__ unsigned long long pack2(float lo, float hi) {
    unsigned long long r;
    asm("mov.b64 %0, {%1, %2};" : "=l"(r) : "f"(lo), "f"(hi));
    return r;
}
__device__ __forceinline__ void ffma2(unsigned long long &d,
                                      unsigned long long a,
                                      unsigned long long b) {
    asm("fma.rn.f32x2 %0, %1, %2, %0;" : "+l"(d) : "l"(a), "l"(b));
}
__device__ __forceinline__ float2 unpack2(unsigned long long v) {
    float2 f;
    asm("mov.b64 {%0, %1}, %2;" : "=f"(f.x), "=f"(f.y) : "l"(v));
    return f;
}

/* ---------------- Kernel 1: xp = inputs @ W_ih + b  ->  out[0:LBH) ------- */
/* A: [M=LSEQ*BDIM, K=DDIM] row-major; W: [K, N=HDIM] row-major.            */
/* 128x128 CTA tile, BK=16, 256 threads, 8x8 per thread, FFMA2 inner loop.  */

__global__ void __launch_bounds__(256, 2) xp_gemm(
    const float* __restrict__ A, const float* __restrict__ W,
    const float* __restrict__ bias, float* __restrict__ C)
{
    __shared__ float As[16][132];   /* A tile transposed, padded            */
    __shared__ float Bs[16][128];

    const int tid = threadIdx.x;
    const int bm = blockIdx.y * 128;
    const int bn = blockIdx.x * 128;
    const int tx = tid & 15, ty = tid >> 4;

    const int ar = tid >> 2, af = (tid & 3) << 2;     /* A: row 0..63, col f4 */
    const int br = tid >> 5, bc = (tid & 31) << 2;    /* B: row 0..7,  col f4 */

    unsigned long long acc[8][4];
    {   /* init accumulators with bias (applied exactly once) */
        const float* bb = bias + bn + tx * 8;
        unsigned long long b0 = pack2(bb[0], bb[1]);
        unsigned long long b1 = pack2(bb[2], bb[3]);
        unsigned long long b2 = pack2(bb[4], bb[5]);
        unsigned long long b3 = pack2(bb[6], bb[7]);
        #pragma unroll
        for (int i = 0; i < 8; i++) {
            acc[i][0] = b0; acc[i][1] = b1; acc[i][2] = b2; acc[i][3] = b3;
        }
    }

    for (int kt = 0; kt < DDIM; kt += 16) {
        float4 a0 = *(const float4*)(A + (size_t)(bm + ar)      * DDIM + kt + af);
        float4 a1 = *(const float4*)(A + (size_t)(bm + ar + 64) * DDIM + kt + af);
        float4 b0 = *(const float4*)(W + (size_t)(kt + br)     * HDIM + bn + bc);
        float4 b1 = *(const float4*)(W + (size_t)(kt + br + 8) * HDIM + bn + bc);
        __syncthreads();
        As[af + 0][ar] = a0.x; As[af + 1][ar] = a0.y;
        As[af + 2][ar] = a0.z; As[af + 3][ar] = a0.w;
        As[af + 0][ar + 64] = a1.x; As[af + 1][ar + 64] = a1.y;
        As[af + 2][ar + 64] = a1.z; As[af + 3][ar + 64] = a1.w;
        *(float4*)&Bs[br][bc]     = b0;
        *(float4*)&Bs[br + 8][bc] = b1;
        __syncthreads();

        #pragma unroll
        for (int k = 0; k < 16; k++) {
            float4 av0 = *(const float4*)&As[k][ty * 8];
            float4 av1 = *(const float4*)&As[k][ty * 8 + 4];
            const unsigned long long* wb =
                (const unsigned long long*)&Bs[k][tx * 8];
            unsigned long long w0 = wb[0], w1 = wb[1], w2 = wb[2], w3 = wb[3];
            float a[8] = {av0.x, av0.y, av0.z, av0.w,
                          av1.x, av1.y, av1.z, av1.w};
            #pragma unroll
            for (int i = 0; i < 8; i++) {
                unsigned long long ai = splat2(a[i]);
                ffma2(acc[i][0], ai, w0);
                ffma2(acc[i][1], ai, w1);
                ffma2(acc[i][2], ai, w2);
                ffma2(acc[i][3], ai, w3);
            }
        }
    }

    #pragma unroll
    for (int i = 0; i < 8; i++) {
        int m = bm + ty * 8 + i;
        float2 r0 = unpack2(acc[i][0]);
        float2 r1 = unpack2(acc[i][1]);
        float2 r2 = unpack2(acc[i][2]);
        float2 r3 = unpack2(acc[i][3]);
        float* cp = C + (size_t)m * HDIM + bn + tx * 8;
        *(float4*)(cp)     = make_float4(r0.x, r0.y, r1.x, r1.y);
        *(float4*)(cp + 4) = make_float4(r2.x, r2.y, r3.x, r3.y);
    }
}

/* ---------------- Kernel 2a: split-K step GEMM --------------------------- */
/* partial[kc] += h[128 x Kchunk] @ Whh[Kchunk x 128-tile].                 */
/* grid = (16 N-tiles, 8 K-chunks) = 128 CTAs, 256 thr, 8x8 per thread.     */

__global__ void __launch_bounds__(256, 2) rnn_gemm(
    const float* __restrict__ Whh, const float* __restrict__ out, int t)
{
    __shared__ float As[16][132];
    __shared__ float Bs[16][128];

    const float* __restrict__ A = out + (size_t)(t - 1) * BH;  /* h [128xH] */

    const int tid = threadIdx.x;
    const int bn = blockIdx.x * 128;
    const int ks = blockIdx.y * KCHUNK;
    const int tx = tid & 15, ty = tid >> 4;

    const int ar = tid >> 2, af = (tid & 3) << 2;
    const int br = tid >> 5, bc = (tid & 31) << 2;

    unsigned long long acc[8][4];
    #pragma unroll
    for (int i = 0; i < 8; i++)
        acc[i][0] = acc[i][1] = acc[i][2] = acc[i][3] = 0ull;

    for (int kt = ks; kt < ks + KCHUNK; kt += 16) {
        float4 a0 = *(const float4*)(A + (size_t)(ar)      * HDIM + kt + af);
        float4 a1 = *(const float4*)(A + (size_t)(ar + 64) * HDIM + kt + af);
        float4 b0 = *(const float4*)(Whh + (size_t)(kt + br)     * HDIM + bn + bc);
        float4 b1 = *(const float4*)(Whh + (size_t)(kt + br + 8) * HDIM + bn + bc);
        __syncthreads();
        As[af + 0][ar] = a0.x; As[af + 1][ar] = a0.y;
        As[af + 2][ar] = a0.z; As[af + 3][ar] = a0.w;
        As[af + 0][ar + 64] = a1.x; As[af + 1][ar + 64] = a1.y;
        As[af + 2][ar + 64] = a1.z; As[af + 3][ar + 64] = a1.w;
        *(float4*)&Bs[br][bc]     = b0;
        *(float4*)&Bs[br + 8][bc] = b1;
        __syncthreads();

        #pragma unroll
        for (int k = 0; k < 16; k++) {
            float4 av0 = *(const float4*)&As[k][ty * 8];
            float4 av1 = *(const float4*)&As[k][ty * 8 + 4];
            const unsigned long long* wb =
                (const unsigned long long*)&Bs[k][tx * 8];
            unsigned long long w0 = wb[0], w1 = wb[1], w2 = wb[2], w3 = wb[3];
            float a[8] = {av0.x, av0.y, av0.z, av0.w,
                          av1.x, av1.y, av1.z, av1.w};
            #pragma unroll
            for (int i = 0; i < 8; i++) {
                unsigned long long ai = splat2(a[i]);
                ffma2(acc[i][0], ai, w0);
                ffma2(acc[i][1], ai, w1);
                ffma2(acc[i][2], ai, w2);
                ffma2(acc[i][3], ai, w3);
            }
        }
    }

    float* P = g_part + (size_t)blockIdx.y * BH;
    #pragma unroll
    for (int i = 0; i < 8; i++) {
        int m = ty * 8 + i;
        float2 r0 = unpack2(acc[i][0]);
        float2 r1 = unpack2(acc[i][1]);
        float2 r2 = unpack2(acc[i][2]);
        float2 r3 = unpack2(acc[i][3]);
        float* cp = P + (size_t)m * HDIM + bn + tx * 8;
        *(float4*)(cp)     = make_float4(r0.x, r0.y, r1.x, r1.y);
        *(float4*)(cp + 4) = make_float4(r2.x, r2.y, r3.x, r3.y);
    }
}

/* ---------------- Kernel 2b: out[t] = tanh(xp + sum of partials) --------- */

__global__ void __launch_bounds__(256) reduce_tanh(float* __restrict__ out, int t)
{
    const int i = blockIdx.x * blockDim.x + threadIdx.x;   /* float4 index */
    float4* o = (float4*)(out + (size_t)t * BH) + i;
    float4 v = *o;
    const float4* P = (const float4*)g_part;
    #pragma unroll
    for (int s = 0; s < KSPLIT; s++) {
        float4 p = P[(size_t)s * (BH / 4) + i];
        v.x += p.x; v.y += p.y; v.z += p.z; v.w += p.w;
    }
    v.x = tanhf(v.x); v.y = tanhf(v.y);
    v.z = tanhf(v.z); v.w = tanhf(v.w);
    *o = v;
}

/* ---------------- Kernel 3: step 0 is just tanh(xp[0]) (h0 = 0) ---------- */

__global__ void tanh0(float* __restrict__ out) {
    int i = blockIdx.x * blockDim.x + threadIdx.x;
    if (i < BH) out[i] = tanhf(out[i]);
}

/* ---------------- Kernel 4: final_state = outputs[L-1] ------------------- */

__global__ void copy_final(float* __restrict__ out) {
    int i = blockIdx.x * blockDim.x + threadIdx.x;
    if (i < BH) out[(size_t)LBH + i] = out[(size_t)(LSEQ - 1) * BH + i];
}

/* ---------------- launch ------------------------------------------------- */

extern "C" void kernel_launch(void* const* d_in, const int* in_sizes, int n_in,
                              void* d_out, int out_size) {
    const float* inputs = (const float*)d_in[0];
    const float* W_ih   = (const float*)d_in[1];
    const float* W_hh   = (const float*)d_in[2];
    const float* bias   = (const float*)d_in[3];
    float* out = (float*)d_out;

    /* xp = inputs @ W_ih + b, written straight into the outputs slab */
    dim3 grid(HDIM / 128, (LSEQ * BDIM) / 128);   /* (16, 256) */
    xp_gemm<<<grid, 256>>>(inputs, W_ih, bias, out);

    /* t = 0: h0 = 0, so out[0] = tanh(xp[0]) */
    tanh0<<<(BH + 255) / 256, 256>>>(out);

    /* t = 1..L-1: split-K GEMM + fused reduce/tanh */
    dim3 sgrid(HDIM / 128, KSPLIT);               /* (16, 8) = 128 CTAs */
    for (int t = 1; t < LSEQ; t++) {
        rnn_gemm<<<sgrid, 256>>>(W_hh, out, t);
        reduce_tanh<<<BH / 4 / 256, 256>>>(out, t);
    }

    /* trailing final_state, if the output buffer includes it */
    if (out_size >= LBH + BH)
        copy_final<<<(BH + 255) / 256, 256>>>(out);
}

// round 5
// speedup vs baseline: 2.0844x; 1.2477x over previous
#include <cuda_runtime.h>
#include <cuda_bf16.h>
#include <math.h>
#include <stdint.h>

#define LSEQ 256
#define BDIM 128
#define DDIM 2048
#define HDIM 2048
#define BH   (BDIM * HDIM)      /* 262144 */
#define LBH  (LSEQ * BH)        /* 67108864 */

#define KSPLIT 8
#define KC (HDIM / KSPLIT)      /* 256 k per CTA */
#define KB 32                   /* k sub-chunk   */
#define NCHUNK (KC / KB)        /* 8             */
#define ASTRIDE 40              /* bf16; 80B rows, ldmatrix conflict-free */
#define BSTRIDE 136             /* bf16; 272B rows, conflict-free        */

/* device scratch: bf16 hi/lo planes of W_hh + split-K partials */
__device__ __nv_bfloat16 g_Whi[(size_t)HDIM * HDIM];   /* 8 MB */
__device__ __nv_bfloat16 g_Wlo[(size_t)HDIM * HDIM];   /* 8 MB */
__device__ float g_part[(size_t)KSPLIT * BH];          /* 8 MB */

/* ---------------- packed f32x2 helpers (xp_gemm) ------------------------- */

__device__ __forceinline__ unsigned long long splat2(float x) {
    unsigned long long r;
    asm("mov.b64 %0, {%1, %1};" : "=l"(r) : "f"(x));
    return r;
}
__device__ __forceinline__ unsigned long long pack2(float lo, float hi) {
    unsigned long long r;
    asm("mov.b64 %0, {%1, %2};" : "=l"(r) : "f"(lo), "f"(hi));
    return r;
}
__device__ __forceinline__ void ffma2(unsigned long long &d,
                                      unsigned long long a,
                                      unsigned long long b) {
    asm("fma.rn.f32x2 %0, %1, %2, %0;" : "+l"(d) : "l"(a), "l"(b));
}
__device__ __forceinline__ float2 unpack2(unsigned long long v) {
    float2 f;
    asm("mov.b64 {%0, %1}, %2;" : "=f"(f.x), "=f"(f.y) : "l"(v));
    return f;
}

/* ---------------- mma helpers -------------------------------------------- */

__device__ __forceinline__ uint32_t smem_u32(const void* p) {
    uint32_t a;
    asm("{ .reg .u64 t; cvta.to.shared.u64 t, %1; cvt.u32.u64 %0, t; }"
        : "=r"(a) : "l"(p));
    return a;
}
__device__ __forceinline__ void ldsm4(uint32_t* r, uint32_t addr) {
    asm volatile("ldmatrix.sync.aligned.m8n8.x4.shared.b16 {%0,%1,%2,%3}, [%4];"
                 : "=r"(r[0]), "=r"(r[1]), "=r"(r[2]), "=r"(r[3]) : "r"(addr));
}
__device__ __forceinline__ void ldsm4t(uint32_t* r, uint32_t addr) {
    asm volatile("ldmatrix.sync.aligned.m8n8.x4.trans.shared.b16 {%0,%1,%2,%3}, [%4];"
                 : "=r"(r[0]), "=r"(r[1]), "=r"(r[2]), "=r"(r[3]) : "r"(addr));
}
__device__ __forceinline__ void mma_bf16(float* d, const uint32_t* a,
                                         const uint32_t* b) {
    asm volatile(
        "mma.sync.aligned.m16n8k16.row.col.f32.bf16.bf16.f32 "
        "{%0,%1,%2,%3}, {%4,%5,%6,%7}, {%8,%9}, {%0,%1,%2,%3};"
        : "+f"(d[0]), "+f"(d[1]), "+f"(d[2]), "+f"(d[3])
        : "r"(a[0]), "r"(a[1]), "r"(a[2]), "r"(a[3]), "r"(b[0]), "r"(b[1]));
}
/* two floats -> packed bf16x2 hi plane + bf16x2 lo (residual) plane */
__device__ __forceinline__ void cvt_hilo(float x, float y,
                                         uint32_t &hi, uint32_t &lo) {
    __nv_bfloat16 hx = __float2bfloat16_rn(x);
    __nv_bfloat16 hy = __float2bfloat16_rn(y);
    float rx = x - __bfloat162float(hx);
    float ry = y - __bfloat162float(hy);
    __nv_bfloat16 lx = __float2bfloat16_rn(rx);
    __nv_bfloat16 ly = __float2bfloat16_rn(ry);
    hi = (uint32_t)__bfloat16_as_ushort(hx) |
         ((uint32_t)__bfloat16_as_ushort(hy) << 16);
    lo = (uint32_t)__bfloat16_as_ushort(lx) |
         ((uint32_t)__bfloat16_as_ushort(ly) << 16);
}

/* ---------------- Kernel 0: W_hh -> bf16 hi/lo planes -------------------- */

__global__ void __launch_bounds__(256) w_prep(const float* __restrict__ W) {
    size_t i = ((size_t)blockIdx.x * 256 + threadIdx.x) * 4;
    float4 v = *(const float4*)(W + i);
    uint32_t h0, l0, h1, l1;
    cvt_hilo(v.x, v.y, h0, l0);
    cvt_hilo(v.z, v.w, h1, l1);
    *(uint2*)(g_Whi + i) = make_uint2(h0, h1);
    *(uint2*)(g_Wlo + i) = make_uint2(l0, l1);
}

/* ---------------- Kernel 1: xp = inputs @ W_ih + b (fp32 FFMA2) ---------- */

__global__ void __launch_bounds__(256, 2) xp_gemm(
    const float* __restrict__ A, const float* __restrict__ W,
    const float* __restrict__ bias, float* __restrict__ C)
{
    __shared__ float As[16][132];
    __shared__ float Bs[16][128];

    const int tid = threadIdx.x;
    const int bm = blockIdx.y * 128;
    const int bn = blockIdx.x * 128;
    const int tx = tid & 15, ty = tid >> 4;
    const int ar = tid >> 2, af = (tid & 3) << 2;
    const int br = tid >> 5, bc = (tid & 31) << 2;

    unsigned long long acc[8][4];
    {
        const float* bb = bias + bn + tx * 8;
        unsigned long long b0 = pack2(bb[0], bb[1]);
        unsigned long long b1 = pack2(bb[2], bb[3]);
        unsigned long long b2 = pack2(bb[4], bb[5]);
        unsigned long long b3 = pack2(bb[6], bb[7]);
        #pragma unroll
        for (int i = 0; i < 8; i++) {
            acc[i][0] = b0; acc[i][1] = b1; acc[i][2] = b2; acc[i][3] = b3;
        }
    }

    for (int kt = 0; kt < DDIM; kt += 16) {
        float4 a0 = *(const float4*)(A + (size_t)(bm + ar)      * DDIM + kt + af);
        float4 a1 = *(const float4*)(A + (size_t)(bm + ar + 64) * DDIM + kt + af);
        float4 b0 = *(const float4*)(W + (size_t)(kt + br)     * HDIM + bn + bc);
        float4 b1 = *(const float4*)(W + (size_t)(kt + br + 8) * HDIM + bn + bc);
        __syncthreads();
        As[af + 0][ar] = a0.x; As[af + 1][ar] = a0.y;
        As[af + 2][ar] = a0.z; As[af + 3][ar] = a0.w;
        As[af + 0][ar + 64] = a1.x; As[af + 1][ar + 64] = a1.y;
        As[af + 2][ar + 64] = a1.z; As[af + 3][ar + 64] = a1.w;
        *(float4*)&Bs[br][bc]     = b0;
        *(float4*)&Bs[br + 8][bc] = b1;
        __syncthreads();

        #pragma unroll
        for (int k = 0; k < 16; k++) {
            float4 av0 = *(const float4*)&As[k][ty * 8];
            float4 av1 = *(const float4*)&As[k][ty * 8 + 4];
            const unsigned long long* wb =
                (const unsigned long long*)&Bs[k][tx * 8];
            unsigned long long w0 = wb[0], w1 = wb[1], w2 = wb[2], w3 = wb[3];
            float a[8] = {av0.x, av0.y, av0.z, av0.w,
                          av1.x, av1.y, av1.z, av1.w};
            #pragma unroll
            for (int i = 0; i < 8; i++) {
                unsigned long long ai = splat2(a[i]);
                ffma2(acc[i][0], ai, w0);
                ffma2(acc[i][1], ai, w1);
                ffma2(acc[i][2], ai, w2);
                ffma2(acc[i][3], ai, w3);
            }
        }
    }

    #pragma unroll
    for (int i = 0; i < 8; i++) {
        int m = bm + ty * 8 + i;
        float2 r0 = unpack2(acc[i][0]);
        float2 r1 = unpack2(acc[i][1]);
        float2 r2 = unpack2(acc[i][2]);
        float2 r3 = unpack2(acc[i][3]);
        float* cp = C + (size_t)m * HDIM + bn + tx * 8;
        *(float4*)(cp)     = make_float4(r0.x, r0.y, r1.x, r1.y);
        *(float4*)(cp + 4) = make_float4(r2.x, r2.y, r3.x, r3.y);
    }
}

/* ---------------- Kernel 2a: warp-mma scan GEMM -------------------------- */
/* grid (16 N-tiles, 8 K-splits) = 128 CTAs, 256 thr = 8 warps (4M x 2N).  */
/* partial[ks] = h[128 x 256k] @ W[256k x 128n], bf16 hi/lo 3-pass,         */
/* fp32 accum via mma.sync.m16n8k16.                                        */

__global__ void __launch_bounds__(256) rnn_mma(const float* __restrict__ out, int t)
{
    __shared__ __align__(16) __nv_bfloat16 Ah[BDIM][ASTRIDE];
    __shared__ __align__(16) __nv_bfloat16 Al[BDIM][ASTRIDE];
    __shared__ __align__(16) __nv_bfloat16 Bh[KB][BSTRIDE];
    __shared__ __align__(16) __nv_bfloat16 Bl[KB][BSTRIDE];

    const int tid  = threadIdx.x;
    const int lane = tid & 31, wid = tid >> 5;
    const int wm = wid & 3, wn = wid >> 2;
    const int bn = blockIdx.x * 128;
    const int ks = blockIdx.y * KC;
    const float* __restrict__ h = out + (size_t)(t - 1) * BH;

    /* staging thread mapping (conflict-free SMEM store phases) */
    const int arow = tid & 127, aseg = (tid >> 7) * 16;   /* k floats    */
    const int brow = tid & 31,  bseg = (tid >> 5) * 16;   /* n bf16      */

    /* ldmatrix per-lane byte offsets */
    const uint32_t ah_b = smem_u32(&Ah[0][0]);
    const uint32_t al_b = smem_u32(&Al[0][0]);
    const uint32_t bh_b = smem_u32(&Bh[0][0]);
    const uint32_t bl_b = smem_u32(&Bl[0][0]);
    const uint32_t a_off =
        (uint32_t)((32 * wm + (lane & 15)) * ASTRIDE + 8 * (lane >> 4)) * 2;
    const uint32_t b_off =
        (uint32_t)(((lane & 7) + 8 * ((lane >> 3) & 1)) * BSTRIDE
                   + 64 * wn + 8 * (lane >> 4)) * 2;

    float acc[2][8][4];
    #pragma unroll
    for (int i = 0; i < 2; i++)
        #pragma unroll
        for (int j = 0; j < 8; j++)
            acc[i][j][0] = acc[i][j][1] = acc[i][j][2] = acc[i][j][3] = 0.f;

    float4 va[4];
    uint4  ub[4];

    /* ---- staging macros ---- */
#define STAGE_LOAD(ck)                                                        \
    {   const float* ap = h + (size_t)arow * HDIM + ks + (ck) * KB + aseg;    \
        va[0] = *(const float4*)(ap);                                         \
        va[1] = *(const float4*)(ap + 4);                                     \
        va[2] = *(const float4*)(ap + 8);                                     \
        va[3] = *(const float4*)(ap + 12);                                    \
        const size_t bo = (size_t)(ks + (ck) * KB + brow) * HDIM + bn + bseg; \
        ub[0] = *(const uint4*)(g_Whi + bo);                                  \
        ub[1] = *(const uint4*)(g_Whi + bo + 8);                              \
        ub[2] = *(const uint4*)(g_Wlo + bo);                                  \
        ub[3] = *(const uint4*)(g_Wlo + bo + 8);                              \
    }

#define STAGE_STORE()                                                         \
    {   uint32_t hi[8], lo[8];                                                \
        cvt_hilo(va[0].x, va[0].y, hi[0], lo[0]);                             \
        cvt_hilo(va[0].z, va[0].w, hi[1], lo[1]);                             \
        cvt_hilo(va[1].x, va[1].y, hi[2], lo[2]);                             \
        cvt_hilo(va[1].z, va[1].w, hi[3], lo[3]);                             \
        cvt_hilo(va[2].x, va[2].y, hi[4], lo[4]);                             \
        cvt_hilo(va[2].z, va[2].w, hi[5], lo[5]);                             \
        cvt_hilo(va[3].x, va[3].y, hi[6], lo[6]);                             \
        cvt_hilo(va[3].z, va[3].w, hi[7], lo[7]);                             \
        *(uint4*)&Ah[arow][aseg]     = make_uint4(hi[0], hi[1], hi[2], hi[3]);\
        *(uint4*)&Ah[arow][aseg + 8] = make_uint4(hi[4], hi[5], hi[6], hi[7]);\
        *(uint4*)&Al[arow][aseg]     = make_uint4(lo[0], lo[1], lo[2], lo[3]);\
        *(uint4*)&Al[arow][aseg + 8] = make_uint4(lo[4], lo[5], lo[6], lo[7]);\
        *(uint4*)&Bh[brow][bseg]     = ub[0];                                 \
        *(uint4*)&Bh[brow][bseg + 8] = ub[1];                                 \
        *(uint4*)&Bl[brow][bseg]     = ub[2];                                 \
        *(uint4*)&Bl[brow][bseg + 8] = ub[3];                                 \
    }

    STAGE_LOAD(0);
    STAGE_STORE();
    __syncthreads();

    for (int ck = 0; ck < NCHUNK; ck++) {
        const bool more = (ck + 1 < NCHUNK);
        if (more) STAGE_LOAD(ck + 1);

        /* compute current chunk: 2 x k16 steps */
        #pragma unroll
        for (int kk = 0; kk < 2; kk++) {
            const uint32_t ak = (uint32_t)(kk * 16 * 2);            /* +16 cols */
            const uint32_t bk = (uint32_t)(kk * 16 * BSTRIDE * 2);  /* +16 rows */
            uint32_t afh[2][4], afl[2][4];
            #pragma unroll
            for (int mt = 0; mt < 2; mt++) {
                uint32_t mo = (uint32_t)(16 * mt * ASTRIDE * 2);
                ldsm4(afh[mt], ah_b + a_off + mo + ak);
                ldsm4(afl[mt], al_b + a_off + mo + ak);
            }
            uint32_t bfh[4][4], bfl[4][4];
            #pragma unroll
            for (int nt = 0; nt < 4; nt++) {
                uint32_t no = (uint32_t)(16 * nt * 2);
                ldsm4t(bfh[nt], bh_b + b_off + no + bk);
                ldsm4t(bfl[nt], bl_b + b_off + no + bk);
            }
            #pragma unroll
            for (int mt = 0; mt < 2; mt++)
                #pragma unroll
                for (int j = 0; j < 8; j++) {
                    const int nt = j >> 1, hf = (j & 1) * 2;
                    mma_bf16(acc[mt][j], afh[mt], &bfh[nt][hf]);
                    mma_bf16(acc[mt][j], afh[mt], &bfl[nt][hf]);
                    mma_bf16(acc[mt][j], afl[mt], &bfh[nt][hf]);
                }
        }

        if (more) {
            __syncthreads();
            STAGE_STORE();
            __syncthreads();
        }
    }

    /* epilogue: write 128x128 partial */
    float* P = g_part + (size_t)blockIdx.y * BH + bn + 64 * wn;
    const int r0 = lane >> 2, c0 = 2 * (lane & 3);
    #pragma unroll
    for (int mt = 0; mt < 2; mt++)
        #pragma unroll
        for (int j = 0; j < 8; j++) {
            float* p = P + (size_t)(32 * wm + 16 * mt + r0) * HDIM + 8 * j + c0;
            *(float2*)p = make_float2(acc[mt][j][0], acc[mt][j][1]);
            *(float2*)(p + 8 * HDIM) = make_float2(acc[mt][j][2], acc[mt][j][3]);
        }
#undef STAGE_LOAD
#undef STAGE_STORE
}

/* ---------------- Kernel 2b: out[t] = tanh(xp + sum partials) ------------ */

__global__ void __launch_bounds__(256) reduce_tanh(float* __restrict__ out, int t)
{
    const int i = blockIdx.x * blockDim.x + threadIdx.x;   /* float4 index */
    float4* o = (float4*)(out + (size_t)t * BH) + i;
    float4 v = *o;
    const float4* P = (const float4*)g_part;
    #pragma unroll
    for (int s = 0; s < KSPLIT; s++) {
        float4 p = P[(size_t)s * (BH / 4) + i];
        v.x += p.x; v.y += p.y; v.z += p.z; v.w += p.w;
    }
    v.x = tanhf(v.x); v.y = tanhf(v.y);
    v.z = tanhf(v.z); v.w = tanhf(v.w);
    *o = v;
}

/* ---------------- Kernel 3/4: step-0 tanh, final state ------------------- */

__global__ void tanh0(float* __restrict__ out) {
    int i = blockIdx.x * blockDim.x + threadIdx.x;
    if (i < BH) out[i] = tanhf(out[i]);
}
__global__ void copy_final(float* __restrict__ out) {
    int i = blockIdx.x * blockDim.x + threadIdx.x;
    if (i < BH) out[(size_t)LBH + i] = out[(size_t)(LSEQ - 1) * BH + i];
}

/* ---------------- launch ------------------------------------------------- */

extern "C" void kernel_launch(void* const* d_in, const int* in_sizes, int n_in,
                              void* d_out, int out_size) {
    const float* inputs = (const float*)d_in[0];
    const float* W_ih   = (const float*)d_in[1];
    const float* W_hh   = (const float*)d_in[2];
    const float* bias   = (const float*)d_in[3];
    float* out = (float*)d_out;

    /* W_hh -> bf16 hi/lo planes (recomputed every call; deterministic) */
    w_prep<<<(HDIM * HDIM / 4) / 256, 256>>>(W_hh);

    /* xp = inputs @ W_ih + b, straight into the outputs slab */
    dim3 grid(HDIM / 128, (LSEQ * BDIM) / 128);
    xp_gemm<<<grid, 256>>>(inputs, W_ih, bias, out);

    /* t = 0: h0 = 0 */
    tanh0<<<(BH + 255) / 256, 256>>>(out);

    /* scan on tensor cores (warp mma) */
    for (int t = 1; t < LSEQ; t++) {
        rnn_mma<<<dim3(HDIM / 128, KSPLIT), 256>>>(out, t);
        reduce_tanh<<<BH / 4 / 256, 256>>>(out, t);
    }

    if (out_size >= LBH + BH)
        copy_final<<<(BH + 255) / 256, 256>>>(out);
}

// round 7
// speedup vs baseline: 2.6009x; 1.2478x over previous
#include <cuda_runtime.h>
#include <cuda_bf16.h>
#include <math.h>
#include <stdint.h>

#define LSEQ 256
#define BDIM 128
#define DDIM 2048
#define HDIM 2048
#define BH   (BDIM * HDIM)      /* 262144 */
#define LBH  (LSEQ * BH)        /* 67108864 */

#define KSPLIT 8
#define KC 256                  /* k per CTA        */
#define KB 32                   /* k sub-chunk      */
#define NCHUNK (KC / KB)        /* 8                */
#define NTILES 16
#define ASTR 40                 /* A row stride, bf16 (80 B, 16B-mult) */
#define WSTR 136                /* W row stride, bf16 (272 B)          */

/* dynamic SMEM layout (bytes) */
#define OFF_WH 0
#define OFF_WL 69632            /* 256*136*2          */
#define OFF_AH 139264
#define OFF_AL 159744           /* + 2*128*40*2       */
#define DSMEM  180224
#define ABUF   10240            /* one A buffer, one plane */

/* device scratch */
__device__ float g_part[(size_t)KSPLIT * BH];   /* 8 MB  */
__device__ __nv_bfloat16 g_hhi[BH];             /* 512 KB */
__device__ __nv_bfloat16 g_hlo[BH];             /* 512 KB */
__device__ unsigned g_count = 0;                /* barrier counter */

/* ---------------- packed f32x2 helpers (xp_gemm) ------------------------- */

__device__ __forceinline__ unsigned long long splat2(float x) {
    unsigned long long r;
    asm("mov.b64 %0, {%1, %1};" : "=l"(r) : "f"(x));
    return r;
}
__device__ __forceinline__ unsigned long long pack2(float lo, float hi) {
    unsigned long long r;
    asm("mov.b64 %0, {%1, %2};" : "=l"(r) : "f"(lo), "f"(hi));
    return r;
}
__device__ __forceinline__ void ffma2(unsigned long long &d,
                                      unsigned long long a,
                                      unsigned long long b) {
    asm("fma.rn.f32x2 %0, %1, %2, %0;" : "+l"(d) : "l"(a), "l"(b));
}
__device__ __forceinline__ float2 unpack2(unsigned long long v) {
    float2 f;
    asm("mov.b64 {%0, %1}, %2;" : "=f"(f.x), "=f"(f.y) : "l"(v));
    return f;
}

/* ---------------- mma helpers -------------------------------------------- */

__device__ __forceinline__ uint32_t smem_u32(const void* p) {
    uint32_t a;
    asm("{ .reg .u64 t; cvta.to.shared.u64 t, %1; cvt.u32.u64 %0, t; }"
        : "=r"(a) : "l"(p));
    return a;
}
__device__ __forceinline__ void ldsm4(uint32_t* r, uint32_t addr) {
    asm volatile("ldmatrix.sync.aligned.m8n8.x4.shared.b16 {%0,%1,%2,%3}, [%4];"
                 : "=r"(r[0]), "=r"(r[1]), "=r"(r[2]), "=r"(r[3]) : "r"(addr));
}
__device__ __forceinline__ void ldsm4t(uint32_t* r, uint32_t addr) {
    asm volatile("ldmatrix.sync.aligned.m8n8.x4.trans.shared.b16 {%0,%1,%2,%3}, [%4];"
                 : "=r"(r[0]), "=r"(r[1]), "=r"(r[2]), "=r"(r[3]) : "r"(addr));
}
__device__ __forceinline__ void mma_bf16(float* d, const uint32_t* a,
                                         const uint32_t* b) {
    asm volatile(
        "mma.sync.aligned.m16n8k16.row.col.f32.bf16.bf16.f32 "
        "{%0,%1,%2,%3}, {%4,%5,%6,%7}, {%8,%9}, {%0,%1,%2,%3};"
        : "+f"(d[0]), "+f"(d[1]), "+f"(d[2]), "+f"(d[3])
        : "r"(a[0]), "r"(a[1]), "r"(a[2]), "r"(a[3]), "r"(b[0]), "r"(b[1]));
}
__device__ __forceinline__ void cvt_hilo(float x, float y,
                                         uint32_t &hi, uint32_t &lo) {
    __nv_bfloat16 hx = __float2bfloat16_rn(x);
    __nv_bfloat16 hy = __float2bfloat16_rn(y);
    float rx = x - __bfloat162float(hx);
    float ry = y - __bfloat162float(hy);
    __nv_bfloat16 lx = __float2bfloat16_rn(rx);
    __nv_bfloat16 ly = __float2bfloat16_rn(ry);
    hi = (uint32_t)__bfloat16_as_ushort(hx) |
         ((uint32_t)__bfloat16_as_ushort(hy) << 16);
    lo = (uint32_t)__bfloat16_as_ushort(lx) |
         ((uint32_t)__bfloat16_as_ushort(ly) << 16);
}

/* ---------------- grid barrier (all 128 CTAs resident) ------------------- */

__device__ __forceinline__ void gbar(unsigned target) {
    __syncthreads();
    if (threadIdx.x == 0) {
        __threadfence();
        atomicAdd(&g_count, 1u);
        unsigned v;
        for (;;) {
            asm volatile("ld.acquire.gpu.global.u32 %0, [%1];"
                         : "=r"(v) : "l"(&g_count) : "memory");
            if (v >= target) break;
            __nanosleep(32);
        }
    }
    __syncthreads();
}

/* ---------------- Kernel 1: xp = inputs @ W_ih + b (fp32 FFMA2) ---------- */

__global__ void __launch_bounds__(256, 2) xp_gemm(
    const float* __restrict__ A, const float* __restrict__ W,
    const float* __restrict__ bias, float* __restrict__ C)
{
    __shared__ float As[16][132];
    __shared__ float Bs[16][128];

    const int tid = threadIdx.x;
    const int bm = blockIdx.y * 128;
    const int bn = blockIdx.x * 128;
    const int tx = tid & 15, ty = tid >> 4;
    const int ar = tid >> 2, af = (tid & 3) << 2;
    const int br = tid >> 5, bc = (tid & 31) << 2;

    unsigned long long acc[8][4];
    {
        const float* bb = bias + bn + tx * 8;
        unsigned long long b0 = pack2(bb[0], bb[1]);
        unsigned long long b1 = pack2(bb[2], bb[3]);
        unsigned long long b2 = pack2(bb[4], bb[5]);
        unsigned long long b3 = pack2(bb[6], bb[7]);
        #pragma unroll
        for (int i = 0; i < 8; i++) {
            acc[i][0] = b0; acc[i][1] = b1; acc[i][2] = b2; acc[i][3] = b3;
        }
    }

    for (int kt = 0; kt < DDIM; kt += 16) {
        float4 a0 = *(const float4*)(A + (size_t)(bm + ar)      * DDIM + kt + af);
        float4 a1 = *(const float4*)(A + (size_t)(bm + ar + 64) * DDIM + kt + af);
        float4 b0 = *(const float4*)(W + (size_t)(kt + br)     * HDIM + bn + bc);
        float4 b1 = *(const float4*)(W + (size_t)(kt + br + 8) * HDIM + bn + bc);
        __syncthreads();
        As[af + 0][ar] = a0.x; As[af + 1][ar] = a0.y;
        As[af + 2][ar] = a0.z; As[af + 3][ar] = a0.w;
        As[af + 0][ar + 64] = a1.x; As[af + 1][ar + 64] = a1.y;
        As[af + 2][ar + 64] = a1.z; As[af + 3][ar + 64] = a1.w;
        *(float4*)&Bs[br][bc]     = b0;
        *(float4*)&Bs[br + 8][bc] = b1;
        __syncthreads();

        #pragma unroll
        for (int k = 0; k < 16; k++) {
            float4 av0 = *(const float4*)&As[k][ty * 8];
            float4 av1 = *(const float4*)&As[k][ty * 8 + 4];
            const unsigned long long* wb =
                (const unsigned long long*)&Bs[k][tx * 8];
            unsigned long long w0 = wb[0], w1 = wb[1], w2 = wb[2], w3 = wb[3];
            float a[8] = {av0.x, av0.y, av0.z, av0.w,
                          av1.x, av1.y, av1.z, av1.w};
            #pragma unroll
            for (int i = 0; i < 8; i++) {
                unsigned long long ai = splat2(a[i]);
                ffma2(acc[i][0], ai, w0);
                ffma2(acc[i][1], ai, w1);
                ffma2(acc[i][2], ai, w2);
                ffma2(acc[i][3], ai, w3);
            }
        }
    }

    #pragma unroll
    for (int i = 0; i < 8; i++) {
        int m = bm + ty * 8 + i;
        float2 r0 = unpack2(acc[i][0]);
        float2 r1 = unpack2(acc[i][1]);
        float2 r2 = unpack2(acc[i][2]);
        float2 r3 = unpack2(acc[i][3]);
        float* cp = C + (size_t)m * HDIM + bn + tx * 8;
        *(float4*)(cp)     = make_float4(r0.x, r0.y, r1.x, r1.y);
        *(float4*)(cp + 4) = make_float4(r2.x, r2.y, r3.x, r3.y);
    }
}

/* ---------------- Kernel 2: step 0 -> h(0) fp32 + bf16 hi/lo planes ------ */

__global__ void __launch_bounds__(256) tanh0p(float* __restrict__ out) {
    const int i4 = blockIdx.x * 256 + threadIdx.x;     /* BH/4 = 65536 */
    float4* O = (float4*)out;
    float4 v = O[i4];
    v.x = tanhf(v.x); v.y = tanhf(v.y);
    v.z = tanhf(v.z); v.w = tanhf(v.w);
    O[i4] = v;
    uint32_t h0, l0, h1, l1;
    cvt_hilo(v.x, v.y, h0, l0);
    cvt_hilo(v.z, v.w, h1, l1);
    *(uint2*)(g_hhi + (size_t)i4 * 4) = make_uint2(h0, h1);
    *(uint2*)(g_hlo + (size_t)i4 * 4) = make_uint2(l0, l1);
}

/* ---------------- Kernel 3: persistent fused scan ------------------------ */
/* 128 CTAs (1/SM), 256 thr = 8 warps (4m x 2n). CTA bid owns W slice       */
/* (nt = bid&15 -> n cols, ks = bid>>4 -> k rows), resident in SMEM as      */
/* bf16 hi/lo, ldmatrix-ready. Per step: partial = h @ Wslice (3-pass       */
/* hi/lo, fp32 mma accum) -> g_part; barrier; reduce+tanh+reconvert;        */
/* barrier.                                                                 */

__global__ void __launch_bounds__(256) rnn_persist(
    const float* __restrict__ W, float* __restrict__ out)
{
    extern __shared__ char dsm[];
    __nv_bfloat16* Wh = (__nv_bfloat16*)(dsm + OFF_WH);
    __nv_bfloat16* Wl = (__nv_bfloat16*)(dsm + OFF_WL);

    const int tid  = threadIdx.x;
    const int lane = tid & 31, wid = tid >> 5;
    const int wm = wid & 3, wn = wid >> 2;
    const int bid = blockIdx.x;
    const int nt = bid & 15, ks = bid >> 4;
    const int bn = nt * 128, kbase = ks * KC;

    /* ---- load + convert W slice once (256k x 128n) ---- */
    #pragma unroll 1
    for (int i = 0; i < 16; i++) {
        int u = tid + 256 * i;             /* 0..4095: (row, 8-col unit) */
        int row = u >> 4;                  /* k 0..255 */
        int seg = (u & 15) * 8;            /* n offset */
        const float* wp = W + (size_t)(kbase + row) * HDIM + bn + seg;
        float4 f0 = *(const float4*)wp;
        float4 f1 = *(const float4*)(wp + 4);
        uint32_t h0, l0, h1, l1, h2, l2, h3, l3;
        cvt_hilo(f0.x, f0.y, h0, l0);
        cvt_hilo(f0.z, f0.w, h1, l1);
        cvt_hilo(f1.x, f1.y, h2, l2);
        cvt_hilo(f1.z, f1.w, h3, l3);
        *(uint4*)&Wh[row * WSTR + seg] = make_uint4(h0, h1, h2, h3);
        *(uint4*)&Wl[row * WSTR + seg] = make_uint4(l0, l1, l2, l3);
    }

    const uint32_t wh_b = smem_u32(dsm + OFF_WH);
    const uint32_t wl_b = smem_u32(dsm + OFF_WL);
    const uint32_t ah_b = smem_u32(dsm + OFF_AH);
    const uint32_t al_b = smem_u32(dsm + OFF_AL);
    const uint32_t a_off =
        (uint32_t)((32 * wm + (lane & 15)) * ASTR + 8 * (lane >> 4)) * 2;
    const uint32_t b_off =
        (uint32_t)(((lane & 7) + 8 * ((lane >> 3) & 1)) * WSTR
                   + 64 * wn + 8 * (lane >> 4)) * 2;

    /* A staging: thread -> (row=tid>>2 and +64, col seg (tid&3)*8) */
    const int arow = tid >> 2;
    const int aq   = (tid & 3) * 8;
    char* Ah = dsm + OFF_AH;
    char* Al = dsm + OFF_AL;
    const uint32_t asw = (uint32_t)(arow * ASTR + aq) * 2;  /* store offset */

    const size_t r4base = (size_t)bid * 512;   /* reduce: float4 indices */
    const float4* G4 = (const float4*)g_part;
    float* Pbase = g_part + (size_t)ks * BH + bn + 64 * wn;
    const int pr0 = lane >> 2, pc0 = 2 * (lane & 3);

    unsigned bart = 0;
    uint4 pa0, pa1, pl0, pl1;

#define ALOAD(ck) { \
    const size_t o = (size_t)arow * HDIM + kbase + (ck) * KB + aq;            \
    pa0 = *(const uint4*)(g_hhi + o);                                         \
    pa1 = *(const uint4*)(g_hhi + o + (size_t)64 * HDIM);                     \
    pl0 = *(const uint4*)(g_hlo + o);                                         \
    pl1 = *(const uint4*)(g_hlo + o + (size_t)64 * HDIM); }

#define ASTORE(buf) { \
    *(uint4*)(Ah + (buf) * ABUF + asw) = pa0;                                 \
    *(uint4*)(Ah + (buf) * ABUF + asw + 64 * ASTR * 2) = pa1;                 \
    *(uint4*)(Al + (buf) * ABUF + asw) = pl0;                                 \
    *(uint4*)(Al + (buf) * ABUF + asw + 64 * ASTR * 2) = pl1; }

    for (int t = 1; t < LSEQ; t++) {
        /* ================= phase G: partial GEMM ================= */
        float acc[2][8][4];
        #pragma unroll
        for (int i = 0; i < 2; i++)
            #pragma unroll
            for (int j = 0; j < 8; j++)
                acc[i][j][0] = acc[i][j][1] = acc[i][j][2] = acc[i][j][3] = 0.f;

        ALOAD(0);
        ASTORE(0);
        __syncthreads();

        int cur = 0;
        for (int ck = 0; ck < NCHUNK; ck++) {
            const bool more = (ck + 1 < NCHUNK);
            if (more) ALOAD(ck + 1);

            const uint32_t abuf = (uint32_t)cur * ABUF;
            #pragma unroll
            for (int kk = 0; kk < 2; kk++) {
                const uint32_t ak = (uint32_t)(kk * 16 * 2);
                const uint32_t bk = (uint32_t)((ck * KB + kk * 16) * WSTR * 2);
                uint32_t afh[2][4], afl[2][4];
                #pragma unroll
                for (int mt = 0; mt < 2; mt++) {
                    uint32_t mo = (uint32_t)(16 * mt * ASTR * 2);
                    ldsm4(afh[mt], ah_b + abuf + a_off + mo + ak);
                    ldsm4(afl[mt], al_b + abuf + a_off + mo + ak);
                }
                uint32_t bfh[4][4], bfl[4][4];
                #pragma unroll
                for (int n4 = 0; n4 < 4; n4++) {
                    uint32_t no = (uint32_t)(16 * n4 * 2);
                    ldsm4t(bfh[n4], wh_b + bk + b_off + no);
                    ldsm4t(bfl[n4], wl_b + bk + b_off + no);
                }
                #pragma unroll
                for (int mt = 0; mt < 2; mt++)
                    #pragma unroll
                    for (int j = 0; j < 8; j++) {
                        const int n4 = j >> 1, hf = (j & 1) * 2;
                        mma_bf16(acc[mt][j], afh[mt], &bfh[n4][hf]);
                        mma_bf16(acc[mt][j], afh[mt], &bfl[n4][hf]);
                        mma_bf16(acc[mt][j], afl[mt], &bfh[n4][hf]);
                    }
            }

            if (more) {
                cur ^= 1;
                ASTORE(cur);
                __syncthreads();
            }
        }

        /* write 128x128 partial */
        #pragma unroll
        for (int mt = 0; mt < 2; mt++)
            #pragma unroll
            for (int j = 0; j < 8; j++) {
                float* p = Pbase + (size_t)(32 * wm + 16 * mt + pr0) * HDIM
                           + 8 * j + pc0;
                *(float2*)p = make_float2(acc[mt][j][0], acc[mt][j][1]);
                *(float2*)(p + 8 * HDIM) =
                    make_float2(acc[mt][j][2], acc[mt][j][3]);
            }

        bart += 128; gbar(bart);

        /* ================= phase R: reduce + tanh + reconvert ==== */
        {
            float4* O4 = (float4*)(out + (size_t)t * BH);
            #pragma unroll
            for (int r = 0; r < 2; r++) {
                size_t i4 = r4base + r * 256 + tid;
                float4 v = O4[i4];
                #pragma unroll
                for (int s = 0; s < KSPLIT; s++) {
                    float4 p = G4[(size_t)s * (BH / 4) + i4];
                    v.x += p.x; v.y += p.y; v.z += p.z; v.w += p.w;
                }
                v.x = tanhf(v.x); v.y = tanhf(v.y);
                v.z = tanhf(v.z); v.w = tanhf(v.w);
                O4[i4] = v;
                uint32_t h0, l0, h1, l1;
                cvt_hilo(v.x, v.y, h0, l0);
                cvt_hilo(v.z, v.w, h1, l1);
                *(uint2*)(g_hhi + i4 * 4) = make_uint2(h0, h1);
                *(uint2*)(g_hlo + i4 * 4) = make_uint2(l0, l1);
            }
        }

        bart += 128; gbar(bart);
    }
#undef ALOAD
#undef ASTORE
}

/* ---------------- Kernel 4: final_state = outputs[L-1] ------------------- */

__global__ void copy_final(float* __restrict__ out) {
    int i = blockIdx.x * blockDim.x + threadIdx.x;
    if (i < BH) out[(size_t)LBH + i] = out[(size_t)(LSEQ - 1) * BH + i];
}

/* ---------------- launch ------------------------------------------------- */

extern "C" void kernel_launch(void* const* d_in, const int* in_sizes, int n_in,
                              void* d_out, int out_size) {
    const float* inputs = (const float*)d_in[0];
    const float* W_ih   = (const float*)d_in[1];
    const float* W_hh   = (const float*)d_in[2];
    const float* bias   = (const float*)d_in[3];
    float* out = (float*)d_out;

    cudaFuncSetAttribute(rnn_persist,
                         cudaFuncAttributeMaxDynamicSharedMemorySize, DSMEM);

    /* reset the grid-barrier counter (graph-capturable memset node) */
    void* cntp = nullptr;
    cudaGetSymbolAddress(&cntp, g_count);
    cudaMemsetAsync(cntp, 0, sizeof(unsigned));

    /* xp = inputs @ W_ih + b, straight into the outputs slab */
    dim3 grid(HDIM / 128, (LSEQ * BDIM) / 128);
    xp_gemm<<<grid, 256>>>(inputs, W_ih, bias, out);

    /* t = 0: h0 = 0 -> h(0) = tanh(xp[0]); also emit bf16 hi/lo planes */
    tanh0p<<<BH / 4 / 256, 256>>>(out);

    /* persistent fused scan: t = 1..255 */
    rnn_persist<<<KSPLIT * NTILES, 256, DSMEM>>>(W_hh, out);

    if (out_size >= LBH + BH)
        copy_final<<<(BH + 255) / 256, 256>>>(out);
}

// round 9
// speedup vs baseline: 3.0922x; 1.1889x over previous
#include <cuda_runtime.h>
#include <cuda_bf16.h>
#include <math.h>
#include <stdint.h>

#define LSEQ 256
#define BDIM 128
#define DDIM 2048
#define HDIM 2048
#define BH   (BDIM * HDIM)      /* 262144 */
#define LBH  (LSEQ * BH)        /* 67108864 */
#define MTOT (LSEQ * BDIM)      /* 32768 */

#define KSPLIT 8
#define KC 256                  /* k per CTA (scan)  */
#define KB 32                   /* k sub-chunk       */
#define NCHUNK (KC / KB)        /* 8                 */
#define NTILES 16
#define ASTR 40                 /* A row stride, bf16 */
#define WSTR 136                /* W row stride, bf16 */

/* dynamic SMEM layout for rnn_persist (bytes) */
#define OFF_WH 0
#define OFF_WL 69632            /* 256*136*2          */
#define OFF_AH 139264
#define OFF_AL 159744
#define DSMEM  180224
#define ABUF   10240

/* device scratch (kept small: ~25 MB total) */
__device__ float g_part[(size_t)KSPLIT * BH];            /* 8 MB   */
__device__ __nv_bfloat16 g_hhi[BH];                      /* 512 KB */
__device__ __nv_bfloat16 g_hlo[BH];                      /* 512 KB */
__device__ __nv_bfloat16 g_wih_hi[(size_t)DDIM * HDIM];  /* 8 MB   */
__device__ __nv_bfloat16 g_wih_lo[(size_t)DDIM * HDIM];  /* 8 MB   */
__device__ unsigned g_count = 0;

/* ---------------- mma helpers -------------------------------------------- */

__device__ __forceinline__ uint32_t smem_u32(const void* p) {
    uint32_t a;
    asm("{ .reg .u64 t; cvta.to.shared.u64 t, %1; cvt.u32.u64 %0, t; }"
        : "=r"(a) : "l"(p));
    return a;
}
__device__ __forceinline__ void ldsm4(uint32_t* r, uint32_t addr) {
    asm volatile("ldmatrix.sync.aligned.m8n8.x4.shared.b16 {%0,%1,%2,%3}, [%4];"
                 : "=r"(r[0]), "=r"(r[1]), "=r"(r[2]), "=r"(r[3]) : "r"(addr));
}
__device__ __forceinline__ void ldsm4t(uint32_t* r, uint32_t addr) {
    asm volatile("ldmatrix.sync.aligned.m8n8.x4.trans.shared.b16 {%0,%1,%2,%3}, [%4];"
                 : "=r"(r[0]), "=r"(r[1]), "=r"(r[2]), "=r"(r[3]) : "r"(addr));
}
__device__ __forceinline__ void mma_bf16(float* d, const uint32_t* a,
                                         const uint32_t* b) {
    asm volatile(
        "mma.sync.aligned.m16n8k16.row.col.f32.bf16.bf16.f32 "
        "{%0,%1,%2,%3}, {%4,%5,%6,%7}, {%8,%9}, {%0,%1,%2,%3};"
        : "+f"(d[0]), "+f"(d[1]), "+f"(d[2]), "+f"(d[3])
        : "r"(a[0]), "r"(a[1]), "r"(a[2]), "r"(a[3]), "r"(b[0]), "r"(b[1]));
}
__device__ __forceinline__ void cvt_hilo(float x, float y,
                                         uint32_t &hi, uint32_t &lo) {
    __nv_bfloat16 hx = __float2bfloat16_rn(x);
    __nv_bfloat16 hy = __float2bfloat16_rn(y);
    float rx = x - __bfloat162float(hx);
    float ry = y - __bfloat162float(hy);
    __nv_bfloat16 lx = __float2bfloat16_rn(rx);
    __nv_bfloat16 ly = __float2bfloat16_rn(ry);
    hi = (uint32_t)__bfloat16_as_ushort(hx) |
         ((uint32_t)__bfloat16_as_ushort(hy) << 16);
    lo = (uint32_t)__bfloat16_as_ushort(lx) |
         ((uint32_t)__bfloat16_as_ushort(ly) << 16);
}

/* ---------------- grid barrier (all 128 CTAs resident) ------------------- */

__device__ __forceinline__ void gbar(unsigned target) {
    __syncthreads();
    if (threadIdx.x == 0) {
        __threadfence();
        atomicAdd(&g_count, 1u);
        unsigned v;
        for (;;) {
            asm volatile("ld.acquire.gpu.global.u32 %0, [%1];"
                         : "=r"(v) : "l"(&g_count) : "memory");
            if (v >= target) break;
            __nanosleep(32);
        }
    }
    __syncthreads();
}

/* ---------------- Kernel P: fp32 -> bf16 hi/lo plane split (W_ih only) --- */

__global__ void __launch_bounds__(256) split_planes(
    const float* __restrict__ src, __nv_bfloat16* __restrict__ dhi,
    __nv_bfloat16* __restrict__ dlo)
{
    size_t i = ((size_t)blockIdx.x * 256 + threadIdx.x) * 4;
    float4 v = *(const float4*)(src + i);
    uint32_t h0, l0, h1, l1;
    cvt_hilo(v.x, v.y, h0, l0);
    cvt_hilo(v.z, v.w, h1, l1);
    *(uint2*)(dhi + i) = make_uint2(h0, h1);
    *(uint2*)(dlo + i) = make_uint2(l0, l1);
}

/* ---------------- Kernel 1: xp = inputs @ W_ih + b via warp mma ---------- */
/* grid (16 N-tiles, 256 M-tiles), 256 thr = 8 warps (4m x 2n).             */
/* A = inputs fp32, converted to bf16 hi/lo in-flight during staging.       */
/* B = pre-split g_wih planes. 3-pass hi/lo, fp32 accum; C = acc + bias.    */

__global__ void __launch_bounds__(256) xp_mma(
    const float* __restrict__ X, const float* __restrict__ bias,
    float* __restrict__ C)
{
    __shared__ __align__(16) __nv_bfloat16 Ah[BDIM][ASTR];
    __shared__ __align__(16) __nv_bfloat16 Al[BDIM][ASTR];
    __shared__ __align__(16) __nv_bfloat16 Bh[KB][WSTR];
    __shared__ __align__(16) __nv_bfloat16 Bl[KB][WSTR];

    const int tid  = threadIdx.x;
    const int lane = tid & 31, wid = tid >> 5;
    const int wm = wid & 3, wn = wid >> 2;
    const int bn = blockIdx.x * 128;
    const int bm = blockIdx.y * 128;

    const int arow = tid & 127, aseg = (tid >> 7) * 16;   /* k floats   */
    const int brow = tid & 31,  bseg = (tid >> 5) * 16;   /* n bf16     */

    const uint32_t ah_b = smem_u32(&Ah[0][0]);
    const uint32_t al_b = smem_u32(&Al[0][0]);
    const uint32_t bh_b = smem_u32(&Bh[0][0]);
    const uint32_t bl_b = smem_u32(&Bl[0][0]);
    const uint32_t a_off =
        (uint32_t)((32 * wm + (lane & 15)) * ASTR + 8 * (lane >> 4)) * 2;
    const uint32_t b_off =
        (uint32_t)(((lane & 7) + 8 * ((lane >> 3) & 1)) * WSTR
                   + 64 * wn + 8 * (lane >> 4)) * 2;

    float acc[2][8][4];
    #pragma unroll
    for (int i = 0; i < 2; i++)
        #pragma unroll
        for (int j = 0; j < 8; j++)
            acc[i][j][0] = acc[i][j][1] = acc[i][j][2] = acc[i][j][3] = 0.f;

    float4 va[4];
    uint4  ub[4];

#define XLOAD(ck)                                                             \
    {   const float* ap = X + (size_t)(bm + arow) * DDIM + (ck) * KB + aseg;  \
        va[0] = *(const float4*)(ap);                                         \
        va[1] = *(const float4*)(ap + 4);                                     \
        va[2] = *(const float4*)(ap + 8);                                     \
        va[3] = *(const float4*)(ap + 12);                                    \
        const size_t bo = (size_t)((ck) * KB + brow) * HDIM + bn + bseg;      \
        ub[0] = *(const uint4*)(g_wih_hi + bo);                               \
        ub[1] = *(const uint4*)(g_wih_hi + bo + 8);                           \
        ub[2] = *(const uint4*)(g_wih_lo + bo);                               \
        ub[3] = *(const uint4*)(g_wih_lo + bo + 8);                           \
    }
#define XSTORE()                                                              \
    {   uint32_t hi[8], lo[8];                                                \
        cvt_hilo(va[0].x, va[0].y, hi[0], lo[0]);                             \
        cvt_hilo(va[0].z, va[0].w, hi[1], lo[1]);                             \
        cvt_hilo(va[1].x, va[1].y, hi[2], lo[2]);                             \
        cvt_hilo(va[1].z, va[1].w, hi[3], lo[3]);                             \
        cvt_hilo(va[2].x, va[2].y, hi[4], lo[4]);                             \
        cvt_hilo(va[2].z, va[2].w, hi[5], lo[5]);                             \
        cvt_hilo(va[3].x, va[3].y, hi[6], lo[6]);                             \
        cvt_hilo(va[3].z, va[3].w, hi[7], lo[7]);                             \
        *(uint4*)&Ah[arow][aseg]     = make_uint4(hi[0], hi[1], hi[2], hi[3]);\
        *(uint4*)&Ah[arow][aseg + 8] = make_uint4(hi[4], hi[5], hi[6], hi[7]);\
        *(uint4*)&Al[arow][aseg]     = make_uint4(lo[0], lo[1], lo[2], lo[3]);\
        *(uint4*)&Al[arow][aseg + 8] = make_uint4(lo[4], lo[5], lo[6], lo[7]);\
        *(uint4*)&Bh[brow][bseg]     = ub[0];                                 \
        *(uint4*)&Bh[brow][bseg + 8] = ub[1];                                 \
        *(uint4*)&Bl[brow][bseg]     = ub[2];                                 \
        *(uint4*)&Bl[brow][bseg + 8] = ub[3];                                 \
    }

    XLOAD(0);
    XSTORE();
    __syncthreads();

    const int NCH = DDIM / KB;     /* 64 */
    for (int ck = 0; ck < NCH; ck++) {
        const bool more = (ck + 1 < NCH);
        if (more) XLOAD(ck + 1);

        #pragma unroll
        for (int kk = 0; kk < 2; kk++) {
            const uint32_t ak = (uint32_t)(kk * 16 * 2);
            const uint32_t bk = (uint32_t)(kk * 16 * WSTR * 2);
            uint32_t afh[2][4], afl[2][4];
            #pragma unroll
            for (int mt = 0; mt < 2; mt++) {
                uint32_t mo = (uint32_t)(16 * mt * ASTR * 2);
                ldsm4(afh[mt], ah_b + a_off + mo + ak);
                ldsm4(afl[mt], al_b + a_off + mo + ak);
            }
            uint32_t bfh[4][4], bfl[4][4];
            #pragma unroll
            for (int n4 = 0; n4 < 4; n4++) {
                uint32_t no = (uint32_t)(16 * n4 * 2);
                ldsm4t(bfh[n4], bh_b + b_off + no + bk);
                ldsm4t(bfl[n4], bl_b + b_off + no + bk);
            }
            #pragma unroll
            for (int mt = 0; mt < 2; mt++)
                #pragma unroll
                for (int j = 0; j < 8; j++) {
                    const int n4 = j >> 1, hf = (j & 1) * 2;
                    mma_bf16(acc[mt][j], afh[mt], &bfh[n4][hf]);
                    mma_bf16(acc[mt][j], afh[mt], &bfl[n4][hf]);
                    mma_bf16(acc[mt][j], afl[mt], &bfh[n4][hf]);
                }
        }

        if (more) {
            __syncthreads();
            XSTORE();
            __syncthreads();
        }
    }

    /* epilogue: C = acc + bias */
    float* P = C + (size_t)bm * HDIM + bn + 64 * wn;
    const int r0 = lane >> 2, c0 = 2 * (lane & 3);
    #pragma unroll
    for (int mt = 0; mt < 2; mt++)
        #pragma unroll
        for (int j = 0; j < 8; j++) {
            const int cc = 64 * wn + 8 * j + c0;
            float b0 = bias[bn + cc], b1 = bias[bn + cc + 1];
            float* p = P + (size_t)(32 * wm + 16 * mt + r0) * HDIM + 8 * j + c0;
            *(float2*)p = make_float2(acc[mt][j][0] + b0, acc[mt][j][1] + b1);
            *(float2*)(p + 8 * HDIM) =
                make_float2(acc[mt][j][2] + b0, acc[mt][j][3] + b1);
        }
#undef XLOAD
#undef XSTORE
}

/* ---------------- Kernel 2: step 0 -> h(0) fp32 + bf16 hi/lo planes ------ */

__global__ void __launch_bounds__(256) tanh0p(float* __restrict__ out) {
    const int i4 = blockIdx.x * 256 + threadIdx.x;
    float4* O = (float4*)out;
    float4 v = O[i4];
    v.x = tanhf(v.x); v.y = tanhf(v.y);
    v.z = tanhf(v.z); v.w = tanhf(v.w);
    O[i4] = v;
    uint32_t h0, l0, h1, l1;
    cvt_hilo(v.x, v.y, h0, l0);
    cvt_hilo(v.z, v.w, h1, l1);
    *(uint2*)(g_hhi + (size_t)i4 * 4) = make_uint2(h0, h1);
    *(uint2*)(g_hlo + (size_t)i4 * 4) = make_uint2(l0, l1);
}

/* ---------------- Kernel 3: persistent fused scan (unchanged, R7) -------- */

__global__ void __launch_bounds__(256) rnn_persist(
    const float* __restrict__ W, float* __restrict__ out)
{
    extern __shared__ char dsm[];
    __nv_bfloat16* Wh = (__nv_bfloat16*)(dsm + OFF_WH);
    __nv_bfloat16* Wl = (__nv_bfloat16*)(dsm + OFF_WL);

    const int tid  = threadIdx.x;
    const int lane = tid & 31, wid = tid >> 5;
    const int wm = wid & 3, wn = wid >> 2;
    const int bid = blockIdx.x;
    const int nt = bid & 15, ks = bid >> 4;
    const int bn = nt * 128, kbase = ks * KC;

    #pragma unroll 1
    for (int i = 0; i < 16; i++) {
        int u = tid + 256 * i;
        int row = u >> 4;
        int seg = (u & 15) * 8;
        const float* wp = W + (size_t)(kbase + row) * HDIM + bn + seg;
        float4 f0 = *(const float4*)wp;
        float4 f1 = *(const float4*)(wp + 4);
        uint32_t h0, l0, h1, l1, h2, l2, h3, l3;
        cvt_hilo(f0.x, f0.y, h0, l0);
        cvt_hilo(f0.z, f0.w, h1, l1);
        cvt_hilo(f1.x, f1.y, h2, l2);
        cvt_hilo(f1.z, f1.w, h3, l3);
        *(uint4*)&Wh[row * WSTR + seg] = make_uint4(h0, h1, h2, h3);
        *(uint4*)&Wl[row * WSTR + seg] = make_uint4(l0, l1, l2, l3);
    }

    const uint32_t wh_b = smem_u32(dsm + OFF_WH);
    const uint32_t wl_b = smem_u32(dsm + OFF_WL);
    const uint32_t ah_b = smem_u32(dsm + OFF_AH);
    const uint32_t al_b = smem_u32(dsm + OFF_AL);
    const uint32_t a_off =
        (uint32_t)((32 * wm + (lane & 15)) * ASTR + 8 * (lane >> 4)) * 2;
    const uint32_t b_off =
        (uint32_t)(((lane & 7) + 8 * ((lane >> 3) & 1)) * WSTR
                   + 64 * wn + 8 * (lane >> 4)) * 2;

    const int arow = tid >> 2;
    const int aq   = (tid & 3) * 8;
    char* Ah = dsm + OFF_AH;
    char* Al = dsm + OFF_AL;
    const uint32_t asw = (uint32_t)(arow * ASTR + aq) * 2;

    const size_t r4base = (size_t)bid * 512;
    const float4* G4 = (const float4*)g_part;
    float* Pbase = g_part + (size_t)ks * BH + bn + 64 * wn;
    const int pr0 = lane >> 2, pc0 = 2 * (lane & 3);

    unsigned bart = 0;
    uint4 pa0, pa1, pl0, pl1;

#define ALOAD(ck) { \
    const size_t o = (size_t)arow * HDIM + kbase + (ck) * KB + aq;            \
    pa0 = *(const uint4*)(g_hhi + o);                                         \
    pa1 = *(const uint4*)(g_hhi + o + (size_t)64 * HDIM);                     \
    pl0 = *(const uint4*)(g_hlo + o);                                         \
    pl1 = *(const uint4*)(g_hlo + o + (size_t)64 * HDIM); }

#define ASTORE(buf) { \
    *(uint4*)(Ah + (buf) * ABUF + asw) = pa0;                                 \
    *(uint4*)(Ah + (buf) * ABUF + asw + 64 * ASTR * 2) = pa1;                 \
    *(uint4*)(Al + (buf) * ABUF + asw) = pl0;                                 \
    *(uint4*)(Al + (buf) * ABUF + asw + 64 * ASTR * 2) = pl1; }

    for (int t = 1; t < LSEQ; t++) {
        float acc[2][8][4];
        #pragma unroll
        for (int i = 0; i < 2; i++)
            #pragma unroll
            for (int j = 0; j < 8; j++)
                acc[i][j][0] = acc[i][j][1] = acc[i][j][2] = acc[i][j][3] = 0.f;

        ALOAD(0);
        ASTORE(0);
        __syncthreads();

        int cur = 0;
        for (int ck = 0; ck < NCHUNK; ck++) {
            const bool more = (ck + 1 < NCHUNK);
            if (more) ALOAD(ck + 1);

            const uint32_t abuf = (uint32_t)cur * ABUF;
            #pragma unroll
            for (int kk = 0; kk < 2; kk++) {
                const uint32_t ak = (uint32_t)(kk * 16 * 2);
                const uint32_t bk = (uint32_t)((ck * KB + kk * 16) * WSTR * 2);
                uint32_t afh[2][4], afl[2][4];
                #pragma unroll
                for (int mt = 0; mt < 2; mt++) {
                    uint32_t mo = (uint32_t)(16 * mt * ASTR * 2);
                    ldsm4(afh[mt], ah_b + abuf + a_off + mo + ak);
                    ldsm4(afl[mt], al_b + abuf + a_off + mo + ak);
                }
                uint32_t bfh[4][4], bfl[4][4];
                #pragma unroll
                for (int n4 = 0; n4 < 4; n4++) {
                    uint32_t no = (uint32_t)(16 * n4 * 2);
                    ldsm4t(bfh[n4], wh_b + bk + b_off + no);
                    ldsm4t(bfl[n4], wl_b + bk + b_off + no);
                }
                #pragma unroll
                for (int mt = 0; mt < 2; mt++)
                    #pragma unroll
                    for (int j = 0; j < 8; j++) {
                        const int n4 = j >> 1, hf = (j & 1) * 2;
                        mma_bf16(acc[mt][j], afh[mt], &bfh[n4][hf]);
                        mma_bf16(acc[mt][j], afh[mt], &bfl[n4][hf]);
                        mma_bf16(acc[mt][j], afl[mt], &bfh[n4][hf]);
                    }
            }

            if (more) {
                cur ^= 1;
                ASTORE(cur);
                __syncthreads();
            }
        }

        #pragma unroll
        for (int mt = 0; mt < 2; mt++)
            #pragma unroll
            for (int j = 0; j < 8; j++) {
                float* p = Pbase + (size_t)(32 * wm + 16 * mt + pr0) * HDIM
                           + 8 * j + pc0;
                *(float2*)p = make_float2(acc[mt][j][0], acc[mt][j][1]);
                *(float2*)(p + 8 * HDIM) =
                    make_float2(acc[mt][j][2], acc[mt][j][3]);
            }

        bart += 128; gbar(bart);

        {
            float4* O4 = (float4*)(out + (size_t)t * BH);
            #pragma unroll
            for (int r = 0; r < 2; r++) {
                size_t i4 = r4base + r * 256 + tid;
                float4 v = O4[i4];
                #pragma unroll
                for (int s = 0; s < KSPLIT; s++) {
                    float4 p = G4[(size_t)s * (BH / 4) + i4];
                    v.x += p.x; v.y += p.y; v.z += p.z; v.w += p.w;
                }
                v.x = tanhf(v.x); v.y = tanhf(v.y);
                v.z = tanhf(v.z); v.w = tanhf(v.w);
                O4[i4] = v;
                uint32_t h0, l0, h1, l1;
                cvt_hilo(v.x, v.y, h0, l0);
                cvt_hilo(v.z, v.w, h1, l1);
                *(uint2*)(g_hhi + i4 * 4) = make_uint2(h0, h1);
                *(uint2*)(g_hlo + i4 * 4) = make_uint2(l0, l1);
            }
        }

        bart += 128; gbar(bart);
    }
#undef ALOAD
#undef ASTORE
}

/* ---------------- Kernel 4: final_state = outputs[L-1] ------------------- */

__global__ void copy_final(float* __restrict__ out) {
    int i = blockIdx.x * blockDim.x + threadIdx.x;
    if (i < BH) out[(size_t)LBH + i] = out[(size_t)(LSEQ - 1) * BH + i];
}

/* ---------------- launch ------------------------------------------------- */

extern "C" void kernel_launch(void* const* d_in, const int* in_sizes, int n_in,
                              void* d_out, int out_size) {
    const float* inputs = (const float*)d_in[0];
    const float* W_ih   = (const float*)d_in[1];
    const float* W_hh   = (const float*)d_in[2];
    const float* bias   = (const float*)d_in[3];
    float* out = (float*)d_out;

    cudaFuncSetAttribute(rnn_persist,
                         cudaFuncAttributeMaxDynamicSharedMemorySize, DSMEM);

    /* reset grid-barrier counter (graph-capturable) */
    void* cntp = nullptr;
    cudaGetSymbolAddress(&cntp, g_count);
    cudaMemsetAsync(cntp, 0, sizeof(unsigned));

    /* split W_ih into bf16 hi/lo planes (16 MB, once per call) */
    {
        void *wh, *wl;
        cudaGetSymbolAddress(&wh, g_wih_hi);
        cudaGetSymbolAddress(&wl, g_wih_lo);
        split_planes<<<((size_t)DDIM * HDIM / 4) / 256, 256>>>(
            W_ih, (__nv_bfloat16*)wh, (__nv_bfloat16*)wl);
    }

    /* xp = inputs @ W_ih + b on tensor cores (A converted in-flight) */
    xp_mma<<<dim3(HDIM / 128, MTOT / 128), 256>>>(inputs, bias, out);

    /* t = 0: h0 = 0 -> h(0) = tanh(xp[0]); also emit bf16 hi/lo planes */
    tanh0p<<<BH / 4 / 256, 256>>>(out);

    /* persistent fused scan: t = 1..255 */
    rnn_persist<<<KSPLIT * NTILES, 256, DSMEM>>>(W_hh, out);

    if (out_size >= LBH + BH)
        copy_final<<<(BH + 255) / 256, 256>>>(out);
}